// round 1
// baseline (speedup 1.0000x reference)
#include <cuda_runtime.h>

// KMeansClustering: N=30000 points, D=64, K=500, up to 1000 Lloyd iterations.
// Persistent single-kernel design: one block per SM, software grid barrier,
// centroids resident in SMEM, point resident in registers, early exit when
// assignments stop changing (mathematically identical to running all iters).

#define NP        30000
#define DIM       64
#define KC        500
#define MAX_ITERS 1000
#define EPSV      1e-6f
#define TPB       256

// Scratch (device globals: no allocation allowed in kernel_launch)
__device__ float g_cent[KC * DIM];
__device__ float g_csq[KC];
__device__ float g_sums[KC * DIM];
__device__ float g_cnts[KC];
__device__ float g_cnts_out[KC];
__device__ int   g_idx[NP];
__device__ int   g_changed[2];
__device__ unsigned int g_bar_cnt;
__device__ volatile unsigned int g_bar_gen;

// Sense-reversing grid barrier. Safe because grid == #SMs and smem usage
// forces exactly 1 resident block per SM (single wave, all blocks co-resident).
__device__ __forceinline__ void grid_sync() {
    __syncthreads();
    if (threadIdx.x == 0) {
        __threadfence();
        unsigned int gen = g_bar_gen;
        if (atomicAdd(&g_bar_cnt, 1u) == gridDim.x - 1u) {
            g_bar_cnt = 0u;
            __threadfence();
            g_bar_gen = gen + 1u;
        } else {
            while (g_bar_gen == gen) { __nanosleep(64); }
        }
        __threadfence();
    }
    __syncthreads();
}

__global__ void __launch_bounds__(TPB, 1)
kmeans_persistent_kernel(const float* __restrict__ embeds,
                         const float* __restrict__ init_cent,
                         float* __restrict__ out)
{
    extern __shared__ float s_dyn[];
    float* s_cent = s_dyn;            // KC*DIM floats (128000 B)
    float* s_csq  = s_dyn + KC * DIM; // KC floats

    const int tid  = threadIdx.x;
    const int gtid = blockIdx.x * TPB + tid;
    const int nth  = gridDim.x * TPB;

    // ---- init (every launch re-initializes all state: deterministic) ----
    for (int i = gtid; i < KC * DIM; i += nth) {
        g_cent[i] = init_cent[i];
        g_sums[i] = 0.f;
    }
    for (int k = gtid; k < KC; k += nth) {
        g_cnts[k] = 0.f;
        float s = 0.f;
        #pragma unroll 8
        for (int d = 0; d < DIM; ++d) {
            float c = init_cent[k * DIM + d];
            s = fmaf(c, c, s);
        }
        g_csq[k] = s;
    }
    for (int i = gtid; i < NP; i += nth) g_idx[i] = -1;
    if (gtid == 0) { g_changed[0] = 0; g_changed[1] = 0; }

    // ---- load this thread's point into registers (held across all iters) ----
    float4 e[16];
    const bool havep = (gtid < NP);
    if (havep) {
        const float4* ep = (const float4*)(embeds + (size_t)gtid * DIM);
        #pragma unroll
        for (int j = 0; j < 16; ++j) e[j] = ep[j];
    }

    grid_sync();

    for (int iter = 0; iter < MAX_ITERS; ++iter) {
        // ---- stage centroids + ||c||^2 into SMEM ----
        for (int i = tid * 4; i < KC * DIM; i += TPB * 4)
            *(float4*)(s_cent + i) = *(const float4*)(g_cent + i);
        for (int i = tid; i < KC; i += TPB)
            s_csq[i] = g_csq[i];
        __syncthreads();

        // ---- phase 1: argmin over K (drop loop-invariant ||e||^2) ----
        if (havep) {
            float bestv = 3.4e38f;
            int   best  = 0;
            for (int k = 0; k < KC; ++k) {
                const float4* cp = (const float4*)(s_cent + k * DIM);
                float a0 = 0.f, a1 = 0.f, a2 = 0.f, a3 = 0.f;
                #pragma unroll
                for (int j = 0; j < 16; j += 4) {
                    float4 c0 = cp[j + 0];
                    float4 c1 = cp[j + 1];
                    float4 c2 = cp[j + 2];
                    float4 c3 = cp[j + 3];
                    a0 = fmaf(e[j + 0].x, c0.x, a0);
                    a0 = fmaf(e[j + 0].y, c0.y, a0);
                    a0 = fmaf(e[j + 0].z, c0.z, a0);
                    a0 = fmaf(e[j + 0].w, c0.w, a0);
                    a1 = fmaf(e[j + 1].x, c1.x, a1);
                    a1 = fmaf(e[j + 1].y, c1.y, a1);
                    a1 = fmaf(e[j + 1].z, c1.z, a1);
                    a1 = fmaf(e[j + 1].w, c1.w, a1);
                    a2 = fmaf(e[j + 2].x, c2.x, a2);
                    a2 = fmaf(e[j + 2].y, c2.y, a2);
                    a2 = fmaf(e[j + 2].z, c2.z, a2);
                    a2 = fmaf(e[j + 2].w, c2.w, a2);
                    a3 = fmaf(e[j + 3].x, c3.x, a3);
                    a3 = fmaf(e[j + 3].y, c3.y, a3);
                    a3 = fmaf(e[j + 3].z, c3.z, a3);
                    a3 = fmaf(e[j + 3].w, c3.w, a3);
                }
                float dot = (a0 + a1) + (a2 + a3);
                float v = fmaf(-2.f, dot, s_csq[k]);
                if (v < bestv) { bestv = v; best = k; }  // strict <: first-min, matches argmin
            }

            if (g_idx[gtid] != best) atomicOr(&g_changed[iter & 1], 1);
            g_idx[gtid] = best;

            // ---- phase 2: segment sums via vector reductions ----
            float* sp = g_sums + best * DIM;
            #pragma unroll
            for (int j = 0; j < 16; ++j)
                atomicAdd((float4*)(sp + 4 * j), e[j]);
            atomicAdd(&g_cnts[best], 1.0f);
        }

        grid_sync();

        // ---- phase 3: centroid update + ||c||^2, reset accumulators ----
        for (int k = gtid; k < KC; k += nth) {
            float cnt = g_cnts[k];
            g_cnts_out[k] = cnt;
            g_cnts[k] = 0.f;
            float den = cnt + EPSV;
            float csq = 0.f;
            #pragma unroll 8
            for (int d = 0; d < DIM; ++d) {
                float s = g_sums[k * DIM + d];
                float c = s / den;               // exact fp32 div, matches reference
                g_sums[k * DIM + d] = 0.f;
                g_cent[k * DIM + d] = c;
                csq = fmaf(c, c, csq);
            }
            g_csq[k] = csq;
        }

        int ch = g_changed[iter & 1];           // finalized at barrier above; uniform
        if (gtid == 0) g_changed[(iter & 1) ^ 1] = 0;  // prep next iter's flag

        grid_sync();

        // Fixed point reached: all remaining iterations are bit-identical.
        if (ch == 0 && iter > 0) break;
    }

    // ---- write outputs: centroids, idxs (as float), counts ----
    for (int i = gtid; i < KC * DIM; i += nth)
        out[i] = g_cent[i];
    for (int i = gtid; i < NP; i += nth)
        out[KC * DIM + i] = (float)g_idx[i];
    for (int i = gtid; i < KC; i += nth)
        out[KC * DIM + NP + i] = g_cnts_out[i];
}

extern "C" void kernel_launch(void* const* d_in, const int* in_sizes, int n_in,
                              void* d_out, int out_size)
{
    const float* embeds = (const float*)d_in[0];
    const float* initc  = (const float*)d_in[1];
    // Robust to input ordering: embeds has NP*DIM elems, centroids KC*DIM.
    if (n_in >= 2 && in_sizes[0] == KC * DIM && in_sizes[1] == NP * DIM) {
        embeds = (const float*)d_in[1];
        initc  = (const float*)d_in[0];
    }
    float* out = (float*)d_out;

    int dev = 0;
    cudaGetDevice(&dev);
    int nsm = 0;
    cudaDeviceGetAttribute(&nsm, cudaDevAttrMultiProcessorCount, dev);

    size_t smem = (size_t)(KC * DIM + KC) * sizeof(float);  // 130000 B
    cudaFuncSetAttribute(kmeans_persistent_kernel,
                         cudaFuncAttributeMaxDynamicSharedMemorySize, (int)smem);

    kmeans_persistent_kernel<<<nsm, TPB, smem>>>(embeds, initc, out);
}

// round 2
// speedup vs baseline: 1.3286x; 1.3286x over previous
#include <cuda_runtime.h>

// KMeansClustering: N=30000, D=64, K=500, up to 1000 Lloyd iterations.
// Persistent kernel, centroids in SMEM, early exit at assignment fixed point.
// R2 changes: balanced round-robin point->thread map (all 152 SMs active in
// phase 1), k-unrolled x4 argmin with 4 independent FMA accumulator chains.

#define NP        30000
#define DIM       64
#define KC        500
#define MAX_ITERS 1000
#define EPSV      1e-6f
#define TPB       256

__device__ float g_cent[KC * DIM];
__device__ float g_csq[KC];
__device__ float g_sums[KC * DIM];
__device__ float g_cnts[KC];
__device__ float g_cnts_out[KC];
__device__ int   g_idx[NP];
__device__ int   g_changed[2];
__device__ unsigned int g_bar_cnt;
__device__ volatile unsigned int g_bar_gen;

// Sense-reversing grid barrier; grid == #SMs, 1 block/SM (smem-forced), so all
// blocks are co-resident and the spin is safe.
__device__ __forceinline__ void grid_sync() {
    __syncthreads();
    if (threadIdx.x == 0) {
        __threadfence();
        unsigned int gen = g_bar_gen;
        if (atomicAdd(&g_bar_cnt, 1u) == gridDim.x - 1u) {
            g_bar_cnt = 0u;
            __threadfence();
            g_bar_gen = gen + 1u;
        } else {
            while (g_bar_gen == gen) { __nanosleep(64); }
        }
        __threadfence();
    }
    __syncthreads();
}

__global__ void __launch_bounds__(TPB, 1)
kmeans_persistent_kernel(const float* __restrict__ embeds,
                         const float* __restrict__ init_cent,
                         float* __restrict__ out)
{
    extern __shared__ float s_dyn[];
    float* s_cent = s_dyn;            // KC*DIM floats
    float* s_csq  = s_dyn + KC * DIM; // KC floats

    const int tid  = threadIdx.x;
    const int gtid = blockIdx.x * TPB + tid;
    const int nth  = gridDim.x * TPB;

    // Balanced point assignment: block b owns points {b, b+G, b+2G, ...}.
    // Every block gets ~197 points -> all SMs busy in the argmin phase.
    const int p = blockIdx.x + gridDim.x * tid;
    const bool havep = (p < NP);

    // ---- init (re-done every launch: deterministic, graph-replayable) ----
    for (int i = gtid; i < KC * DIM; i += nth) {
        g_cent[i] = init_cent[i];
        g_sums[i] = 0.f;
    }
    for (int k = gtid; k < KC; k += nth) {
        g_cnts[k] = 0.f;
        float s = 0.f;
        #pragma unroll 8
        for (int d = 0; d < DIM; ++d) {
            float c = init_cent[k * DIM + d];
            s = fmaf(c, c, s);
        }
        g_csq[k] = s;
    }
    for (int i = gtid; i < NP; i += nth) g_idx[i] = -1;
    if (gtid == 0) { g_changed[0] = 0; g_changed[1] = 0; }

    // ---- this thread's point lives in registers for the whole run ----
    float4 e[16];
    if (havep) {
        const float4* ep = (const float4*)(embeds + (size_t)p * DIM);
        #pragma unroll
        for (int j = 0; j < 16; ++j) e[j] = ep[j];
    }

    grid_sync();

    for (int iter = 0; iter < MAX_ITERS; ++iter) {
        // ---- stage centroids + ||c||^2 into SMEM ----
        for (int i = tid * 4; i < KC * DIM; i += TPB * 4)
            *(float4*)(s_cent + i) = *(const float4*)(g_cent + i);
        for (int i = tid; i < KC; i += TPB)
            s_csq[i] = g_csq[i];
        __syncthreads();

        // ---- phase 1: argmin_k ( ||c_k||^2 - 2 e.c_k )  (||e||^2 invariant) ----
        if (havep) {
            float bestv = 3.4e38f;
            int   best  = 0;
            #pragma unroll 1
            for (int k = 0; k < KC; k += 4) {       // 500 % 4 == 0
                const float4* c0 = (const float4*)(s_cent + (k + 0) * DIM);
                const float4* c1 = (const float4*)(s_cent + (k + 1) * DIM);
                const float4* c2 = (const float4*)(s_cent + (k + 2) * DIM);
                const float4* c3 = (const float4*)(s_cent + (k + 3) * DIM);
                float a0 = 0.f, a1 = 0.f, a2 = 0.f, a3 = 0.f;
                #pragma unroll
                for (int j = 0; j < 16; ++j) {
                    float4 x0 = c0[j];
                    float4 x1 = c1[j];
                    float4 x2 = c2[j];
                    float4 x3 = c3[j];
                    float4 ej = e[j];
                    a0 = fmaf(ej.x, x0.x, a0);
                    a0 = fmaf(ej.y, x0.y, a0);
                    a0 = fmaf(ej.z, x0.z, a0);
                    a0 = fmaf(ej.w, x0.w, a0);
                    a1 = fmaf(ej.x, x1.x, a1);
                    a1 = fmaf(ej.y, x1.y, a1);
                    a1 = fmaf(ej.z, x1.z, a1);
                    a1 = fmaf(ej.w, x1.w, a1);
                    a2 = fmaf(ej.x, x2.x, a2);
                    a2 = fmaf(ej.y, x2.y, a2);
                    a2 = fmaf(ej.z, x2.z, a2);
                    a2 = fmaf(ej.w, x2.w, a2);
                    a3 = fmaf(ej.x, x3.x, a3);
                    a3 = fmaf(ej.y, x3.y, a3);
                    a3 = fmaf(ej.z, x3.z, a3);
                    a3 = fmaf(ej.w, x3.w, a3);
                }
                float d0 = fmaf(-2.f, a0, s_csq[k + 0]);
                float d1 = fmaf(-2.f, a1, s_csq[k + 1]);
                float d2 = fmaf(-2.f, a2, s_csq[k + 2]);
                float d3 = fmaf(-2.f, a3, s_csq[k + 3]);
                // strict < in ascending k order == jnp.argmin first-min rule
                if (d0 < bestv) { bestv = d0; best = k + 0; }
                if (d1 < bestv) { bestv = d1; best = k + 1; }
                if (d2 < bestv) { bestv = d2; best = k + 2; }
                if (d3 < bestv) { bestv = d3; best = k + 3; }
            }

            if (g_idx[p] != best) atomicOr(&g_changed[iter & 1], 1);
            g_idx[p] = best;

            // ---- phase 2: segment sums (vector global reductions) ----
            float* sp = g_sums + best * DIM;
            #pragma unroll
            for (int j = 0; j < 16; ++j)
                atomicAdd((float4*)(sp + 4 * j), e[j]);
            atomicAdd(&g_cnts[best], 1.0f);
        }

        grid_sync();

        // ---- phase 3: centroid update + ||c||^2, reset accumulators ----
        for (int k = gtid; k < KC; k += nth) {
            float cnt = g_cnts[k];
            g_cnts_out[k] = cnt;
            g_cnts[k] = 0.f;
            float den = cnt + EPSV;
            float csq = 0.f;
            #pragma unroll
            for (int j = 0; j < 16; ++j) {
                float4 s = *(float4*)(g_sums + k * DIM + 4 * j);
                float4 c;
                c.x = s.x / den; c.y = s.y / den;
                c.z = s.z / den; c.w = s.w / den;
                *(float4*)(g_sums + k * DIM + 4 * j) = make_float4(0.f, 0.f, 0.f, 0.f);
                *(float4*)(g_cent + k * DIM + 4 * j) = c;
                csq = fmaf(c.x, c.x, csq);
                csq = fmaf(c.y, c.y, csq);
                csq = fmaf(c.z, c.z, csq);
                csq = fmaf(c.w, c.w, csq);
            }
            g_csq[k] = csq;
        }

        int ch = g_changed[iter & 1];                  // finalized before barrier
        if (gtid == 0) g_changed[(iter & 1) ^ 1] = 0;  // reset next iter's flag

        grid_sync();

        // Assignment fixed point: all remaining iterations are bit-identical.
        if (ch == 0 && iter > 0) break;
    }

    // ---- outputs: centroids [KC*DIM], idxs [NP] (as float), counts [KC] ----
    for (int i = gtid; i < KC * DIM; i += nth)
        out[i] = g_cent[i];
    for (int i = gtid; i < NP; i += nth)
        out[KC * DIM + i] = (float)g_idx[i];
    for (int i = gtid; i < KC; i += nth)
        out[KC * DIM + NP + i] = g_cnts_out[i];
}

extern "C" void kernel_launch(void* const* d_in, const int* in_sizes, int n_in,
                              void* d_out, int out_size)
{
    const float* embeds = (const float*)d_in[0];
    const float* initc  = (const float*)d_in[1];
    if (n_in >= 2 && in_sizes[0] == KC * DIM && in_sizes[1] == NP * DIM) {
        embeds = (const float*)d_in[1];
        initc  = (const float*)d_in[0];
    }
    float* out = (float*)d_out;

    int dev = 0;
    cudaGetDevice(&dev);
    int nsm = 0;
    cudaDeviceGetAttribute(&nsm, cudaDevAttrMultiProcessorCount, dev);

    size_t smem = (size_t)(KC * DIM + KC) * sizeof(float);  // 130 KB
    cudaFuncSetAttribute(kmeans_persistent_kernel,
                         cudaFuncAttributeMaxDynamicSharedMemorySize, (int)smem);

    kmeans_persistent_kernel<<<nsm, TPB, smem>>>(embeds, initc, out);
}

// round 4
// speedup vs baseline: 1.6886x; 1.2709x over previous
#include <cuda_runtime.h>

// KMeans: N=30000, D=64, K=500, Lloyd with assignment-fixed-point early exit.
// R3: 2 points per thread (halves LDS crossbar traffic per FMA — R2 profile
// showed L1/crossbar at 57.6% was the binding pipe), active threads packed
// into warps 0-3 (one per SMSP), 8 independent FMA chains, distributed
// phase-3 centroid update, ballot-elected changed-flag atomics.

#define NP        30000
#define DIM       64
#define KC        500
#define MAX_ITERS 1000
#define EPSV      1e-6f
#define TPB       256

__device__ float g_cent[KC * DIM];
__device__ float g_csq[KC];
__device__ float g_sums[KC * DIM];
__device__ float g_cnts[KC];
__device__ float g_cnts_out[KC];
__device__ int   g_idx[NP];
__device__ int   g_changed[2];
__device__ unsigned int g_bar_cnt;
__device__ volatile unsigned int g_bar_gen;

// Sense-reversing grid barrier; grid == #SMs, 1 block/SM (smem-forced).
__device__ __forceinline__ void grid_sync() {
    __syncthreads();
    if (threadIdx.x == 0) {
        __threadfence();
        unsigned int gen = g_bar_gen;
        if (atomicAdd(&g_bar_cnt, 1u) == gridDim.x - 1u) {
            g_bar_cnt = 0u;
            __threadfence();
            g_bar_gen = gen + 1u;
        } else {
            while (g_bar_gen == gen) { __nanosleep(64); }
        }
        __threadfence();
    }
    __syncthreads();
}

__global__ void __launch_bounds__(TPB, 1)
kmeans_persistent_kernel(const float* __restrict__ embeds,
                         const float* __restrict__ init_cent,
                         float* __restrict__ out)
{
    extern __shared__ float s_dyn[];
    float* s_cent = s_dyn;            // KC*DIM floats (128 KB)
    float* s_csq  = s_dyn + KC * DIM; // KC floats

    const int tid  = threadIdx.x;
    const int gtid = blockIdx.x * TPB + tid;
    const int nth  = gridDim.x * TPB;
    const int G    = gridDim.x;

    // 2 points per thread, round-robin across blocks: p0=b+G*2t, p1=b+G*(2t+1).
    // Active threads are t<=98 -> packed into warps 0..3 (one per SMSP).
    const int p0 = blockIdx.x + G * (2 * tid);
    const int p1 = blockIdx.x + G * (2 * tid + 1);
    const bool v0 = (p0 < NP);
    const bool v1 = (p1 < NP);

    // ---- init ----
    for (int i = gtid; i < KC * DIM; i += nth) {
        g_cent[i] = init_cent[i];
        g_sums[i] = 0.f;
    }
    for (int k = gtid; k < KC; k += nth) {
        g_cnts[k] = 0.f;
        float s = 0.f;
        #pragma unroll 8
        for (int d = 0; d < DIM; ++d) {
            float c = init_cent[k * DIM + d];
            s = fmaf(c, c, s);
        }
        g_csq[k] = s;
    }
    for (int i = gtid; i < NP; i += nth) g_idx[i] = -1;
    if (gtid == 0) { g_changed[0] = 0; g_changed[1] = 0; }

    // ---- both points live in registers for the whole run ----
    float4 e0[16], e1[16];
    if (v0) {
        const float4* ep = (const float4*)(embeds + (size_t)p0 * DIM);
        #pragma unroll
        for (int j = 0; j < 16; ++j) e0[j] = ep[j];
    }
    if (v1) {
        const float4* ep = (const float4*)(embeds + (size_t)p1 * DIM);
        #pragma unroll
        for (int j = 0; j < 16; ++j) e1[j] = ep[j];
    } else {
        #pragma unroll
        for (int j = 0; j < 16; ++j) e1[j] = make_float4(0.f, 0.f, 0.f, 0.f);
    }

    grid_sync();

    for (int iter = 0; iter < MAX_ITERS; ++iter) {
        // ---- stage centroids + ||c||^2 into SMEM ----
        for (int i = tid * 4; i < KC * DIM; i += TPB * 4)
            *(float4*)(s_cent + i) = *(const float4*)(g_cent + i);
        for (int i = tid; i < KC; i += TPB)
            s_csq[i] = g_csq[i];
        __syncthreads();

        // ---- phase 1: argmin_k ( ||c_k||^2 - 2 e.c_k ) for both points ----
        if (v0) {
            float best0v = 3.4e38f, best1v = 3.4e38f;
            int   best0  = 0,       best1  = 0;
            #pragma unroll 1
            for (int k = 0; k < KC; k += 2) {       // 500 % 2 == 0
                const float4* c0 = (const float4*)(s_cent + (k + 0) * DIM);
                const float4* c1 = (const float4*)(s_cent + (k + 1) * DIM);
                // 8 independent chains: 2 pts x 2 centroids x 2 partials
                float a00a = 0.f, a00b = 0.f, a01a = 0.f, a01b = 0.f;
                float a10a = 0.f, a10b = 0.f, a11a = 0.f, a11b = 0.f;
                #pragma unroll
                for (int j = 0; j < 16; ++j) {
                    float4 x0 = c0[j];
                    float4 x1 = c1[j];
                    float4 u = e0[j];
                    float4 w = e1[j];
                    a00a = fmaf(u.x, x0.x, a00a);
                    a00b = fmaf(u.y, x0.y, a00b);
                    a00a = fmaf(u.z, x0.z, a00a);
                    a00b = fmaf(u.w, x0.w, a00b);
                    a01a = fmaf(u.x, x1.x, a01a);
                    a01b = fmaf(u.y, x1.y, a01b);
                    a01a = fmaf(u.z, x1.z, a01a);
                    a01b = fmaf(u.w, x1.w, a01b);
                    a10a = fmaf(w.x, x0.x, a10a);
                    a10b = fmaf(w.y, x0.y, a10b);
                    a10a = fmaf(w.z, x0.z, a10a);
                    a10b = fmaf(w.w, x0.w, a10b);
                    a11a = fmaf(w.x, x1.x, a11a);
                    a11b = fmaf(w.y, x1.y, a11b);
                    a11a = fmaf(w.z, x1.z, a11a);
                    a11b = fmaf(w.w, x1.w, a11b);
                }
                float cs0 = s_csq[k + 0];
                float cs1 = s_csq[k + 1];
                float d00 = fmaf(-2.f, a00a + a00b, cs0);
                float d01 = fmaf(-2.f, a01a + a01b, cs1);
                float d10 = fmaf(-2.f, a10a + a10b, cs0);
                float d11 = fmaf(-2.f, a11a + a11b, cs1);
                // strict <, ascending k == jnp.argmin first-min rule
                if (d00 < best0v) { best0v = d00; best0 = k + 0; }
                if (d01 < best0v) { best0v = d01; best0 = k + 1; }
                if (d10 < best1v) { best1v = d10; best1 = k + 0; }
                if (d11 < best1v) { best1v = d11; best1 = k + 1; }
            }

            // changed-flag: one atomic per warp via ballot
            bool mych = (g_idx[p0] != best0) || (v1 && (g_idx[p1] != best1));
            unsigned int am = __activemask();
            unsigned int bal = __ballot_sync(am, mych);
            if (bal && ((am & (am - 1u) & ~(((unsigned)1 << (threadIdx.x & 31)) - 1u)) == (am & ~(((unsigned)1 << (threadIdx.x & 31)) - 1u) & ~((unsigned)1 << (threadIdx.x & 31))))) {
                // (leader = lowest set lane of am)
            }
            if (bal && ((int)(threadIdx.x & 31) == __ffs(am) - 1))
                atomicOr(&g_changed[iter & 1], 1);

            g_idx[p0] = best0;
            if (v1) g_idx[p1] = best1;

            // ---- phase 2: segment sums (vector global reductions) ----
            {
                float* sp = g_sums + best0 * DIM;
                #pragma unroll
                for (int j = 0; j < 16; ++j)
                    atomicAdd((float4*)(sp + 4 * j), e0[j]);
                atomicAdd(&g_cnts[best0], 1.0f);
            }
            if (v1) {
                float* sp = g_sums + best1 * DIM;
                #pragma unroll
                for (int j = 0; j < 16; ++j)
                    atomicAdd((float4*)(sp + 4 * j), e1[j]);
                atomicAdd(&g_cnts[best1], 1.0f);
            }
        }

        grid_sync();

        // ---- phase 3: centroid update, distributed one k per (block, warp) ----
        {
            const int w    = tid >> 5;
            const int lane = tid & 31;
            const int k    = blockIdx.x + G * w;    // w<4 covers k<608>=KC
            if (w < 4 && k < KC && lane < 16) {
                float cnt = g_cnts[k];
                float den = cnt + EPSV;
                float4 s = *(float4*)(g_sums + k * DIM + 4 * lane);
                float4 c;
                c.x = s.x / den; c.y = s.y / den;
                c.z = s.z / den; c.w = s.w / den;
                *(float4*)(g_sums + k * DIM + 4 * lane) = make_float4(0.f, 0.f, 0.f, 0.f);
                *(float4*)(g_cent + k * DIM + 4 * lane) = c;
                float csq = fmaf(c.x, c.x, fmaf(c.y, c.y, fmaf(c.z, c.z, c.w * c.w)));
                // reduce over 16 lanes
                csq += __shfl_down_sync(0xFFFFu, csq, 8);
                csq += __shfl_down_sync(0xFFFFu, csq, 4);
                csq += __shfl_down_sync(0xFFFFu, csq, 2);
                csq += __shfl_down_sync(0xFFFFu, csq, 1);
                if (lane == 0) {
                    g_csq[k] = csq;
                    g_cnts_out[k] = cnt;
                    g_cnts[k] = 0.f;
                }
            }
        }

        int ch = g_changed[iter & 1];                  // finalized before barrier
        if (gtid == 0) g_changed[(iter & 1) ^ 1] = 0;

        grid_sync();

        if (ch == 0 && iter > 0) break;   // assignment fixed point: done
    }

    // ---- outputs: centroids [KC*DIM], idxs [NP] (float), counts [KC] ----
    for (int i = gtid; i < KC * DIM; i += nth)
        out[i] = g_cent[i];
    for (int i = gtid; i < NP; i += nth)
        out[KC * DIM + i] = (float)g_idx[i];
    for (int i = gtid; i < KC; i += nth)
        out[KC * DIM + NP + i] = g_cnts_out[i];
}

extern "C" void kernel_launch(void* const* d_in, const int* in_sizes, int n_in,
                              void* d_out, int out_size)
{
    const float* embeds = (const float*)d_in[0];
    const float* initc  = (const float*)d_in[1];
    if (n_in >= 2 && in_sizes[0] == KC * DIM && in_sizes[1] == NP * DIM) {
        embeds = (const float*)d_in[1];
        initc  = (const float*)d_in[0];
    }
    float* out = (float*)d_out;

    int dev = 0;
    cudaGetDevice(&dev);
    int nsm = 0;
    cudaDeviceGetAttribute(&nsm, cudaDevAttrMultiProcessorCount, dev);

    size_t smem = (size_t)(KC * DIM + KC) * sizeof(float);  // 130 KB
    cudaFuncSetAttribute(kmeans_persistent_kernel,
                         cudaFuncAttributeMaxDynamicSharedMemorySize, (int)smem);

    kmeans_persistent_kernel<<<nsm, TPB, smem>>>(embeds, initc, out);
}

// round 6
// speedup vs baseline: 1.8998x; 1.1250x over previous
#include <cuda_runtime.h>

// KMeans: N=30000, D=64, K=500, Lloyd, assignment-fixed-point early exit.
// R5: (a) k-range split across the two half-blocks -> ~6.2 active warps/SM
// (2 per SMSP) instead of 3.1, hiding LDS latency at UNCHANGED total
// crossbar/FMA work; (b) packed fma.rn.f32x2 (FFMA2) halves FMA issue slots
// at exact fp32 precision. R4 profile: L1 42% == fma 42%, issue 50% ->
// latency-bound with balanced pipes; this targets issue/latency.

#define NP        30000
#define DIM       64
#define KC        500
#define MAX_ITERS 1000
#define EPSV      1e-6f
#define TPB       256
#define HKC       (KC / 2)   // 250 centroids per half

typedef unsigned long long ull;

#define FMA2(d, a, b, c) \
    asm("fma.rn.f32x2 %0, %1, %2, %3;" : "=l"(d) : "l"(a), "l"(b), "l"(c))

__device__ __forceinline__ float f32x2_hsum(ull v) {
    unsigned int lo, hi;
    asm("mov.b64 {%0, %1}, %2;" : "=r"(lo), "=r"(hi) : "l"(v));
    return __uint_as_float(lo) + __uint_as_float(hi);
}

__device__ float g_cent[KC * DIM];
__device__ float g_csq[KC];
__device__ float g_sums[KC * DIM];
__device__ float g_cnts[KC];
__device__ float g_cnts_out[KC];
__device__ int   g_idx[NP];
__device__ int   g_changed[2];
__device__ unsigned int g_bar_cnt;
__device__ volatile unsigned int g_bar_gen;

// Sense-reversing grid barrier; grid == #SMs, 1 block/SM (smem-forced).
__device__ __forceinline__ void grid_sync() {
    __syncthreads();
    if (threadIdx.x == 0) {
        __threadfence();
        unsigned int gen = g_bar_gen;
        if (atomicAdd(&g_bar_cnt, 1u) == gridDim.x - 1u) {
            g_bar_cnt = 0u;
            __threadfence();
            g_bar_gen = gen + 1u;
        } else {
            while (g_bar_gen == gen) { __nanosleep(64); }
        }
        __threadfence();
    }
    __syncthreads();
}

__global__ void __launch_bounds__(TPB, 1)
kmeans_persistent_kernel(const float* __restrict__ embeds,
                         const float* __restrict__ init_cent,
                         float* __restrict__ out)
{
    extern __shared__ float s_dyn[];
    float* s_cent = s_dyn;                   // KC*DIM floats (128 KB)
    float* s_csq  = s_dyn + KC * DIM;        // KC floats
    float* s_bv0  = s_csq + KC;              // 128: upper-half best value, pt0
    float* s_bv1  = s_bv0 + 128;             // 128: pt1
    int*   s_bi0  = (int*)(s_bv1 + 128);     // 128: upper-half best idx, pt0
    int*   s_bi1  = s_bi0 + 128;             // 128: pt1

    const int tid  = threadIdx.x;
    const int gtid = blockIdx.x * TPB + tid;
    const int nth  = gridDim.x * TPB;
    const int G    = gridDim.x;

    // Two half-blocks scan disjoint k-ranges for the SAME points.
    const int half = tid >> 7;        // 0: k in [0,250), 1: k in [250,500)
    const int ht   = tid & 127;       // index within half
    const int p0   = blockIdx.x + G * (2 * ht);
    const int p1   = blockIdx.x + G * (2 * ht + 1);
    const bool v0  = (p0 < NP);
    const bool v1  = (p1 < NP);
    const int kbase = half * HKC;

    // ---- init ----
    for (int i = gtid; i < KC * DIM; i += nth) {
        g_cent[i] = init_cent[i];
        g_sums[i] = 0.f;
    }
    for (int k = gtid; k < KC; k += nth) {
        g_cnts[k] = 0.f;
        float s = 0.f;
        #pragma unroll 8
        for (int d = 0; d < DIM; ++d) {
            float c = init_cent[k * DIM + d];
            s = fmaf(c, c, s);
        }
        g_csq[k] = s;
    }
    for (int i = gtid; i < NP; i += nth) g_idx[i] = -1;
    if (gtid == 0) { g_changed[0] = 0; g_changed[1] = 0; }

    // ---- both points live in registers (as f32x2 pairs) for the whole run ----
    ulonglong2 e0[16], e1[16];
    if (v0) {
        const ulonglong2* ep = (const ulonglong2*)(embeds + (size_t)p0 * DIM);
        #pragma unroll
        for (int j = 0; j < 16; ++j) e0[j] = ep[j];
    }
    if (v1) {
        const ulonglong2* ep = (const ulonglong2*)(embeds + (size_t)p1 * DIM);
        #pragma unroll
        for (int j = 0; j < 16; ++j) e1[j] = ep[j];
    } else {
        #pragma unroll
        for (int j = 0; j < 16; ++j) { e1[j].x = 0ull; e1[j].y = 0ull; }
    }

    grid_sync();

    for (int iter = 0; iter < MAX_ITERS; ++iter) {
        // ---- stage centroids + ||c||^2 into SMEM ----
        for (int i = tid * 4; i < KC * DIM; i += TPB * 4)
            *(float4*)(s_cent + i) = *(const float4*)(g_cent + i);
        for (int i = tid; i < KC; i += TPB)
            s_csq[i] = g_csq[i];
        __syncthreads();

        float bestv0 = 3.4e38f, bestv1 = 3.4e38f;
        int   besti0 = kbase,   besti1 = kbase;

        if (v0) {
            // ---- phase 1: argmin over this half's 250 centroids ----
            #pragma unroll 1
            for (int kk = 0; kk < HKC; kk += 2) {
                const int k = kbase + kk;
                const ulonglong2* c0 = (const ulonglong2*)(s_cent + (k + 0) * DIM);
                const ulonglong2* c1 = (const ulonglong2*)(s_cent + (k + 1) * DIM);
                // 8 independent f32x2 accumulator chains
                ull a00 = 0, b00 = 0, a01 = 0, b01 = 0;
                ull a10 = 0, b10 = 0, a11 = 0, b11 = 0;
                #pragma unroll
                for (int j = 0; j < 16; ++j) {
                    ulonglong2 x0 = c0[j];
                    ulonglong2 x1 = c1[j];
                    ulonglong2 u = e0[j];
                    ulonglong2 w = e1[j];
                    FMA2(a00, u.x, x0.x, a00);
                    FMA2(b00, u.y, x0.y, b00);
                    FMA2(a01, u.x, x1.x, a01);
                    FMA2(b01, u.y, x1.y, b01);
                    FMA2(a10, w.x, x0.x, a10);
                    FMA2(b10, w.y, x0.y, b10);
                    FMA2(a11, w.x, x1.x, a11);
                    FMA2(b11, w.y, x1.y, b11);
                }
                float cs0 = s_csq[k + 0];
                float cs1 = s_csq[k + 1];
                float d00 = fmaf(-2.f, f32x2_hsum(a00) + f32x2_hsum(b00), cs0);
                float d01 = fmaf(-2.f, f32x2_hsum(a01) + f32x2_hsum(b01), cs1);
                float d10 = fmaf(-2.f, f32x2_hsum(a10) + f32x2_hsum(b10), cs0);
                float d11 = fmaf(-2.f, f32x2_hsum(a11) + f32x2_hsum(b11), cs1);
                // strict <, ascending k == jnp.argmin first-min rule
                if (d00 < bestv0) { bestv0 = d00; besti0 = k + 0; }
                if (d01 < bestv0) { bestv0 = d01; besti0 = k + 1; }
                if (d10 < bestv1) { bestv1 = d10; besti1 = k + 0; }
                if (d11 < bestv1) { bestv1 = d11; besti1 = k + 1; }
            }
        }

        // ---- merge the two halves' argmins (upper half publishes to SMEM) ----
        if (half == 1 && v0) {
            s_bv0[ht] = bestv0;  s_bi0[ht] = besti0;
            s_bv1[ht] = bestv1;  s_bi1[ht] = besti1;
        }
        __syncthreads();

        if (half == 0 && v0) {
            // upper half's ks are all larger -> strict < keeps first-min rule
            float uv0 = s_bv0[ht];
            float uv1 = s_bv1[ht];
            int best0 = besti0, best1 = besti1;
            float bv0f = bestv0, bv1f = bestv1;
            if (uv0 < bv0f) { best0 = s_bi0[ht]; }
            if (uv1 < bv1f) { best1 = s_bi1[ht]; }

            // changed-flag: one atomic per warp via ballot
            bool mych = (g_idx[p0] != best0) || (v1 && (g_idx[p1] != best1));
            unsigned int am  = __activemask();
            unsigned int bal = __ballot_sync(am, mych);
            int leader = __ffs(am) - 1;
            if (bal && ((int)(tid & 31) == leader))
                atomicOr(&g_changed[iter & 1], 1);

            g_idx[p0] = best0;
            if (v1) g_idx[p1] = best1;

            // ---- phase 2: segment sums (vector global reductions) ----
            {
                float* sp = g_sums + best0 * DIM;
                #pragma unroll
                for (int j = 0; j < 16; ++j) {
                    float4 v = *(float4*)&e0[j];
                    atomicAdd((float4*)(sp + 4 * j), v);
                }
                atomicAdd(&g_cnts[best0], 1.0f);
            }
            if (v1) {
                float* sp = g_sums + best1 * DIM;
                #pragma unroll
                for (int j = 0; j < 16; ++j) {
                    float4 v = *(float4*)&e1[j];
                    atomicAdd((float4*)(sp + 4 * j), v);
                }
                atomicAdd(&g_cnts[best1], 1.0f);
            }
        }

        grid_sync();

        // ---- phase 3: centroid update, one k per (block, warp) ----
        {
            const int w    = tid >> 5;
            const int lane = tid & 31;
            const int k    = blockIdx.x + G * w;   // w<4 covers k<608 >= KC
            if (w < 4 && k < KC && lane < 16) {
                float cnt = g_cnts[k];
                float den = cnt + EPSV;
                float4 s = *(float4*)(g_sums + k * DIM + 4 * lane);
                float4 c;
                c.x = s.x / den; c.y = s.y / den;
                c.z = s.z / den; c.w = s.w / den;
                *(float4*)(g_sums + k * DIM + 4 * lane) = make_float4(0.f, 0.f, 0.f, 0.f);
                *(float4*)(g_cent + k * DIM + 4 * lane) = c;
                float csq = fmaf(c.x, c.x, fmaf(c.y, c.y, fmaf(c.z, c.z, c.w * c.w)));
                csq += __shfl_down_sync(0xFFFFu, csq, 8);
                csq += __shfl_down_sync(0xFFFFu, csq, 4);
                csq += __shfl_down_sync(0xFFFFu, csq, 2);
                csq += __shfl_down_sync(0xFFFFu, csq, 1);
                if (lane == 0) {
                    g_csq[k] = csq;
                    g_cnts_out[k] = cnt;
                    g_cnts[k] = 0.f;
                }
            }
        }

        int ch = g_changed[iter & 1];                  // finalized before barrier
        if (gtid == 0) g_changed[(iter & 1) ^ 1] = 0;

        grid_sync();

        if (ch == 0 && iter > 0) break;   // assignment fixed point: done
    }

    // ---- outputs: centroids [KC*DIM], idxs [NP] (float), counts [KC] ----
    for (int i = gtid; i < KC * DIM; i += nth)
        out[i] = g_cent[i];
    for (int i = gtid; i < NP; i += nth)
        out[KC * DIM + i] = (float)g_idx[i];
    for (int i = gtid; i < KC; i += nth)
        out[KC * DIM + NP + i] = g_cnts_out[i];
}

extern "C" void kernel_launch(void* const* d_in, const int* in_sizes, int n_in,
                              void* d_out, int out_size)
{
    const float* embeds = (const float*)d_in[0];
    const float* initc  = (const float*)d_in[1];
    if (n_in >= 2 && in_sizes[0] == KC * DIM && in_sizes[1] == NP * DIM) {
        embeds = (const float*)d_in[1];
        initc  = (const float*)d_in[0];
    }
    float* out = (float*)d_out;

    int dev = 0;
    cudaGetDevice(&dev);
    int nsm = 0;
    cudaDeviceGetAttribute(&nsm, cudaDevAttrMultiProcessorCount, dev);

    // 128KB centroids + csq + merge scratch
    size_t smem = (size_t)(KC * DIM + KC) * sizeof(float)
                + 128 * 2 * sizeof(float) + 128 * 2 * sizeof(int);
    cudaFuncSetAttribute(kmeans_persistent_kernel,
                         cudaFuncAttributeMaxDynamicSharedMemorySize, (int)smem);

    kmeans_persistent_kernel<<<nsm, TPB, smem>>>(embeds, initc, out);
}